// round 15
// baseline (speedup 1.0000x reference)
#include <cuda_runtime.h>
#include <cuda_bf16.h>
#include <cstdint>

#define BB 4
#define SS 2048
#define HH 1024
#define NROWS (BB*SS)
#define LCAP 128
#define HCAP 512

// ---------------------------------------------------------------------------
// Static device scratch
// ---------------------------------------------------------------------------
__device__ __align__(256) float g_VL[(size_t)NROWS * HH];
__device__ float g_a[NROWS];
__device__ float g_b[NROWS];
__device__ __align__(256) __nv_bfloat16 g_Ah[(size_t)NROWS * HH];
__device__ __align__(256) __nv_bfloat16 g_Al[(size_t)NROWS * HH];
__device__ __align__(256) __nv_bfloat16 g_Wh[(size_t)HH * HH];
__device__ __align__(256) __nv_bfloat16 g_Wl[(size_t)HH * HH];
// attention scratch
__device__ float g_sb[BB * SS];
__device__ int   g_si[BB * SS];
__device__ int   g_uni[BB];
__device__ int   g_nheavy[BB];
__device__ int   g_hidx[BB * SS];
__device__ int   g_cnt[NROWS];            // light count; -1 heavy; -2 overflow
__device__ float g_Z[NROWS];
__device__ float g_wl[(size_t)NROWS * LCAP];
__device__ __align__(256) float g_P[(size_t)BB * HCAP * SS];
__device__ float g_Zr[BB * HCAP];

// ---------------------------------------------------------------------------
// helpers
// ---------------------------------------------------------------------------
__device__ __forceinline__ uint32_t smem_u32(const void* p) {
    uint32_t a;
    asm("{ .reg .u64 t; cvta.to.shared.u64 t, %1; cvt.u32.u64 %0, t; }"
        : "=r"(a) : "l"(p));
    return a;
}
__device__ __forceinline__ void cp16(uint32_t dst, const void* src) {
    asm volatile("cp.async.cg.shared.global [%0], [%1], 16;"
                 :: "r"(dst), "l"(src) : "memory");
}
__device__ __forceinline__ void ldsm_x4(uint32_t& r0, uint32_t& r1,
                                        uint32_t& r2, uint32_t& r3,
                                        uint32_t addr) {
    asm volatile("ldmatrix.sync.aligned.m8n8.x4.shared.b16 {%0,%1,%2,%3}, [%4];"
                 : "=r"(r0), "=r"(r1), "=r"(r2), "=r"(r3) : "r"(addr) : "memory");
}
__device__ __forceinline__ void mma_bf16(float* c, const uint32_t* a,
                                         const uint32_t* b) {
    asm volatile(
        "mma.sync.aligned.m16n8k16.row.col.f32.bf16.bf16.f32 "
        "{%0,%1,%2,%3}, {%4,%5,%6,%7}, {%8,%9}, {%0,%1,%2,%3};"
        : "+f"(c[0]), "+f"(c[1]), "+f"(c[2]), "+f"(c[3])
        : "r"(a[0]), "r"(a[1]), "r"(a[2]), "r"(a[3]), "r"(b[0]), "r"(b[1]));
}
__device__ __forceinline__ uint32_t swz128(uint32_t off) {
    return off ^ ((off >> 3) & 0x70);
}

// ---------------------------------------------------------------------------
// K1: rank-1 vectors + hi/lo bf16 split of hs
// ---------------------------------------------------------------------------
__global__ void __launch_bounds__(256) rank1_kernel(
    const float* __restrict__ hs, const float* __restrict__ U,
    const float* __restrict__ V)
{
    const int row = blockIdx.x;
    const int tid = threadIdx.x;
    const float4 h = ((const float4*)(hs + (size_t)row * HH))[tid];

    __nv_bfloat16 h0 = __float2bfloat16(h.x);
    __nv_bfloat16 h1 = __float2bfloat16(h.y);
    __nv_bfloat16 h2 = __float2bfloat16(h.z);
    __nv_bfloat16 h3 = __float2bfloat16(h.w);
    __nv_bfloat162* ph = (__nv_bfloat162*)(g_Ah + (size_t)row * HH + tid * 4);
    __nv_bfloat162* pl = (__nv_bfloat162*)(g_Al + (size_t)row * HH + tid * 4);
    ph[0] = __halves2bfloat162(h0, h1);
    ph[1] = __halves2bfloat162(h2, h3);
    pl[0] = __halves2bfloat162(
        __float2bfloat16(h.x - __bfloat162float(h0)),
        __float2bfloat16(h.y - __bfloat162float(h1)));
    pl[1] = __halves2bfloat162(
        __float2bfloat16(h.z - __bfloat162float(h2)),
        __float2bfloat16(h.w - __bfloat162float(h3)));

    const float4 u = ((const float4*)U)[tid];
    const float4 v = ((const float4*)V)[tid];
    float su = h.x * u.x + h.y * u.y + h.z * u.z + h.w * u.w;
    float sv = h.x * v.x + h.y * v.y + h.z * v.z + h.w * v.w;
    #pragma unroll
    for (int o = 16; o > 0; o >>= 1) {
        su += __shfl_xor_sync(0xffffffffu, su, o);
        sv += __shfl_xor_sync(0xffffffffu, sv, o);
    }
    __shared__ float s_u[8], s_v[8];
    if ((tid & 31) == 0) { s_u[tid >> 5] = su; s_v[tid >> 5] = sv; }
    __syncthreads();
    if (tid == 0) {
        float tu = 0.f, tv = 0.f;
        #pragma unroll
        for (int i = 0; i < 8; i++) { tu += s_u[i]; tv += s_v[i]; }
        g_a[row] = (tu + U[HH]) * 0.125f;
        g_b[row] = tv + V[HH];
    }
}

// ---------------------------------------------------------------------------
// K1b: hi/lo split of value_w
// ---------------------------------------------------------------------------
__global__ void __launch_bounds__(256) wconv_kernel(const float* __restrict__ w)
{
    const int idx = blockIdx.x * 256 + threadIdx.x;
    const float4 x = ((const float4*)w)[idx];
    __nv_bfloat16 h0 = __float2bfloat16(x.x);
    __nv_bfloat16 h1 = __float2bfloat16(x.y);
    __nv_bfloat16 h2 = __float2bfloat16(x.z);
    __nv_bfloat16 h3 = __float2bfloat16(x.w);
    __nv_bfloat162* ph = (__nv_bfloat162*)(g_Wh + (size_t)idx * 4);
    __nv_bfloat162* pl = (__nv_bfloat162*)(g_Wl + (size_t)idx * 4);
    ph[0] = __halves2bfloat162(h0, h1);
    ph[1] = __halves2bfloat162(h2, h3);
    pl[0] = __halves2bfloat162(
        __float2bfloat16(x.x - __bfloat162float(h0)),
        __float2bfloat16(x.y - __bfloat162float(h1)));
    pl[1] = __halves2bfloat162(
        __float2bfloat16(x.z - __bfloat162float(h2)),
        __float2bfloat16(x.w - __bfloat162float(h3)));
}

// ---------------------------------------------------------------------------
// K2: value projection bf16x3 GEMM (unchanged, proven)
// ---------------------------------------------------------------------------
#define AH_OFF 0
#define AL_OFF 16384
#define WH_OFF 32768
#define WL_OFF 49152
#define STAGE_BYTES 65536
#define GEMM_SMEM_TOTAL (2 * STAGE_BYTES)

__device__ __forceinline__ void load_slab(uint32_t sb, int bm, int bn, int k0,
                                          int tid)
{
    const char* a_h = (const char*)g_Ah + (size_t)bm * 2048 + k0 * 2;
    const char* a_l = (const char*)g_Al + (size_t)bm * 2048 + k0 * 2;
    const char* w_h = (const char*)g_Wh + (size_t)bn * 2048 + k0 * 2;
    const char* w_l = (const char*)g_Wl + (size_t)bn * 2048 + k0 * 2;
    #pragma unroll
    for (int i = 0; i < 4; i++) {
        int cid = tid + i * 256;
        int row = cid >> 3;
        int c16 = (cid & 7) * 16;
        uint32_t swz = swz128((uint32_t)(row * 128 + c16));
        size_t goff = (size_t)row * 2048 + c16;
        cp16(sb + AH_OFF + swz, a_h + goff);
        cp16(sb + AL_OFF + swz, a_l + goff);
        cp16(sb + WH_OFF + swz, w_h + goff);
        cp16(sb + WL_OFF + swz, w_l + goff);
    }
}

__global__ void __launch_bounds__(256, 1)
gemm_kernel(const float* __restrict__ bias)
{
    extern __shared__ char smem[];
    const uint32_t smem_base = smem_u32(smem);
    const int tid  = threadIdx.x;
    const int wid  = tid >> 5;
    const int lane = tid & 31;
    const int bm = (blockIdx.x >> 3) * 128;
    const int bn = (blockIdx.x & 7) * 128;
    const int warp_m = (wid & 1) * 64;
    const int warp_n = (wid >> 1) * 32;
    const uint32_t st0 = smem_base;
    const uint32_t st1 = smem_base + STAGE_BYTES;

    float acc[4][4][4];
    #pragma unroll
    for (int i = 0; i < 4; i++)
        #pragma unroll
        for (int j = 0; j < 4; j++)
            #pragma unroll
            for (int q = 0; q < 4; q++) acc[i][j][q] = 0.f;

    uint32_t a_base[4];
    #pragma unroll
    for (int mf = 0; mf < 4; mf++)
        a_base[mf] = swz128((uint32_t)(
            (warp_m + mf * 16 + (lane & 15)) * 128 + ((lane >> 4) & 1) * 16));
    uint32_t b_base[2];
    #pragma unroll
    for (int p = 0; p < 2; p++)
        b_base[p] = swz128((uint32_t)(
            (warp_n + p * 16 + (lane & 7) + ((lane & 16) >> 1)) * 128
            + ((lane & 8) ? 16u : 0u)));

    load_slab(st0, bm, bn, 0, tid);
    asm volatile("cp.async.commit_group;" ::: "memory");
    load_slab(st1, bm, bn, 64, tid);
    asm volatile("cp.async.commit_group;" ::: "memory");

    for (int j = 0; j < 16; j++) {
        const uint32_t sb = (j & 1) ? st1 : st0;
        if (j < 15) asm volatile("cp.async.wait_group 1;" ::: "memory");
        else        asm volatile("cp.async.wait_group 0;" ::: "memory");
        __syncthreads();
        #pragma unroll
        for (int ks = 0; ks < 4; ks++) {
            const uint32_t kso = (uint32_t)(ks * 32);
            uint32_t af[4][4], bh[4][2], bl[4][2];
            #pragma unroll
            for (int mf = 0; mf < 4; mf++)
                ldsm_x4(af[mf][0], af[mf][1], af[mf][2], af[mf][3],
                        sb + AH_OFF + (a_base[mf] ^ kso));
            #pragma unroll
            for (int p = 0; p < 2; p++)
                ldsm_x4(bh[2*p][0], bh[2*p][1], bh[2*p+1][0], bh[2*p+1][1],
                        sb + WH_OFF + (b_base[p] ^ kso));
            #pragma unroll
            for (int mf = 0; mf < 4; mf++)
                #pragma unroll
                for (int nf = 0; nf < 4; nf++)
                    mma_bf16(acc[mf][nf], af[mf], bh[nf]);
            #pragma unroll
            for (int p = 0; p < 2; p++)
                ldsm_x4(bl[2*p][0], bl[2*p][1], bl[2*p+1][0], bl[2*p+1][1],
                        sb + WL_OFF + (b_base[p] ^ kso));
            #pragma unroll
            for (int mf = 0; mf < 4; mf++)
                #pragma unroll
                for (int nf = 0; nf < 4; nf++)
                    mma_bf16(acc[mf][nf], af[mf], bl[nf]);
            #pragma unroll
            for (int mf = 0; mf < 4; mf++)
                ldsm_x4(af[mf][0], af[mf][1], af[mf][2], af[mf][3],
                        sb + AL_OFF + (a_base[mf] ^ kso));
            #pragma unroll
            for (int mf = 0; mf < 4; mf++)
                #pragma unroll
                for (int nf = 0; nf < 4; nf++)
                    mma_bf16(acc[mf][nf], af[mf], bh[nf]);
        }
        __syncthreads();
        if (j + 2 < 16) {
            load_slab(sb, bm, bn, (j + 2) * 64, tid);
            asm volatile("cp.async.commit_group;" ::: "memory");
        }
    }

    const int r0 = bm + warp_m + (lane >> 2);
    const int c0 = bn + warp_n + 2 * (lane & 3);
    #pragma unroll
    for (int nf = 0; nf < 4; nf++) {
        const int c = c0 + nf * 8;
        const float b0 = bias[c], b1 = bias[c + 1];
        #pragma unroll
        for (int mf = 0; mf < 4; mf++) {
            const int r = r0 + mf * 16;
            float2 v0 = { acc[mf][nf][0] + b0, acc[mf][nf][1] + b1 };
            float2 v1 = { acc[mf][nf][2] + b0, acc[mf][nf][3] + b1 };
            *(float2*)(g_VL + (size_t)r * HH + c)       = v0;
            *(float2*)(g_VL + (size_t)(r + 8) * HH + c) = v1;
        }
    }
}

// ---------------------------------------------------------------------------
// K3: per-batch bitonic sort of b (descending, index tie-break) + mask check
// ---------------------------------------------------------------------------
__global__ void __launch_bounds__(1024) sort_kernel(const float* __restrict__ mask)
{
    __shared__ float sb[SS];
    __shared__ int   si[SS];
    __shared__ int   sflag;
    const int batch = blockIdx.x;
    const int tid = threadIdx.x;
    if (tid == 0) sflag = 1;
    __syncthreads();
    const float m0 = mask[batch * SS];
    #pragma unroll
    for (int q = 0; q < 2; q++) {
        int i = tid + q * 1024;
        sb[i] = g_b[batch * SS + i];
        si[i] = i;
        if (mask[batch * SS + i] != m0) atomicAnd(&sflag, 0);
    }
    __syncthreads();
    for (int k = 2; k <= SS; k <<= 1) {
        for (int j = k >> 1; j > 0; j >>= 1) {
            #pragma unroll
            for (int q = 0; q < 2; q++) {
                int i = tid + q * 1024;
                int ixj = i ^ j;
                if (ixj > i) {
                    bool up = ((i & k) == 0);
                    float bi = sb[i], bj = sb[ixj];
                    int ii = si[i], ij = si[ixj];
                    bool less = (bi < bj) || (bi == bj && ii > ij);
                    if (less == up) {
                        sb[i] = bj; sb[ixj] = bi;
                        si[i] = ij; si[ixj] = ii;
                    }
                }
            }
            __syncthreads();
        }
    }
    #pragma unroll
    for (int q = 0; q < 2; q++) {
        int i = tid + q * 1024;
        g_sb[batch * SS + i] = sb[i];
        g_si[batch * SS + i] = si[i];
    }
    if (tid == 0) { g_uni[batch] = sflag; g_nheavy[batch] = 0; }
}

// ---------------------------------------------------------------------------
// K4: classify rows; light weights + Z; heavy list
// ---------------------------------------------------------------------------
__global__ void __launch_bounds__(LCAP) classify_kernel()
{
    const int row = blockIdx.x;
    const int batch = row >> 11;
    if (!g_uni[batch]) return;
    const int tid = threadIdx.x;
    const int lane = tid & 31, wid = tid >> 5;
    const float a = g_a[row];
    const float* sb = g_sb + batch * SS;
    const float bmax = sb[0], bmin = sb[SS - 1];
    __shared__ float red[4];

    int count;
    if (a == 0.f) count = SS;
    else if (a > 0.f) {
        float thr = bmax - 40.f / a;
        int lo = 0, hi = SS;
        while (lo < hi) { int mid = (lo + hi) >> 1;
                          if (sb[mid] >= thr) lo = mid + 1; else hi = mid; }
        count = lo;
    } else {
        float thr = bmin + 40.f / (-a);
        int lo = 0, hi = SS;
        while (lo < hi) { int mid = (lo + hi) >> 1;
                          if (sb[mid] > thr) lo = mid + 1; else hi = mid; }
        count = SS - lo;
    }

    if (count <= LCAP) {
        float w = 0.f;
        if (tid < count) {
            float sv = (a > 0.f) ? sb[tid] : sb[SS - 1 - tid];
            float gz = (a > 0.f) ? a * bmax : a * bmin;
            w = expf(a * sv - gz);
            g_wl[(size_t)row * LCAP + tid] = w;
        }
        float s = w;
        #pragma unroll
        for (int o = 16; o > 0; o >>= 1) s += __shfl_xor_sync(0xffffffffu, s, o);
        if (lane == 0) red[wid] = s;
        __syncthreads();
        if (tid == 0) {
            g_Z[row] = red[0] + red[1] + red[2] + red[3];
            g_cnt[row] = count;
        }
    } else if (tid == 0) {
        int pos = atomicAdd(&g_nheavy[batch], 1);
        if (pos < HCAP) {
            g_hidx[batch * SS + pos] = row & (SS - 1);
            g_cnt[row] = -1;
        } else {
            g_cnt[row] = -2;    // overflow: dense fallback handles this row
        }
    }
}

// ---------------------------------------------------------------------------
// K5: dense fp32 softmax numerators for heavy rows -> g_P, g_Zr
// ---------------------------------------------------------------------------
__global__ void __launch_bounds__(256) pdense_kernel()
{
    const int batch = blockIdx.y;
    const int r = blockIdx.x;
    int nh = g_nheavy[batch]; if (nh > HCAP) nh = HCAP;
    if (r >= nh) return;
    const int srow = g_hidx[batch * SS + r];
    const float a = g_a[(batch << 11) + srow];
    const float* bb = g_b + (batch << 11);
    const int tid = threadIdx.x, lane = tid & 31, wid = tid >> 5;
    __shared__ float red[8];
    const float gmax = fmaxf(a * g_sb[batch * SS], a * g_sb[batch * SS + SS - 1]);

    const size_t base = ((size_t)(batch * HCAP + r)) * SS;
    float lsum = 0.f;
    #pragma unroll
    for (int c = 0; c < 8; c++) {
        int t = c * 256 + tid;
        float w = expf(a * bb[t] - gmax);
        g_P[base + t] = w;
        lsum += w;
    }
    #pragma unroll
    for (int o = 16; o > 0; o >>= 1)
        lsum += __shfl_xor_sync(0xffffffffu, lsum, o);
    if (lane == 0) red[wid] = lsum;
    __syncthreads();
    if (tid == 0) {
        float s = 0.f;
        #pragma unroll
        for (int i = 0; i < 8; i++) s += red[i];
        g_Zr[batch * HCAP + r] = s;
    }
}

// ---------------------------------------------------------------------------
// K6: heavy GEMM  out[srow, j] = (1/Zr) sum_t P[r,t]*VL[t,j]  (fp32 FMA)
// Block: 32 heavy-rows x 128 cols, 256 thr. t-chunks of 32, double buffer.
// ---------------------------------------------------------------------------
#define HVL_FLOATS (32 * 128)
#define HP_STRIDE  36
#define HP_FLOATS  (32 * HP_STRIDE)
#define HCHUNK_FLOATS (HVL_FLOATS + HP_FLOATS)
#define HG_SMEM (2 * HCHUNK_FLOATS * 4)

__device__ __forceinline__ void load_hchunk(uint32_t base, int stage, int batch,
                                            int mt, int j0, int ch, int tid)
{
    uint32_t vb = base + (uint32_t)stage * HCHUNK_FLOATS * 4;
    #pragma unroll
    for (int i = 0; i < 4; i++) {
        int lin = tid + i * 256;
        int tt = lin >> 5;
        int c4 = (lin & 31) * 4;
        const char* src = (const char*)(g_VL
            + ((size_t)(batch * SS + ch * 32 + tt) * HH + j0 + c4));
        cp16(vb + (uint32_t)((tt * 128 + c4) * 4), src);
    }
    {
        int r = tid >> 3, g = tid & 7;
        const char* src = (const char*)(g_P
            + ((size_t)(batch * HCAP + mt * 32 + r) * SS + ch * 32 + g * 4));
        cp16(vb + (uint32_t)((HVL_FLOATS + r * HP_STRIDE + g * 4) * 4), src);
    }
}

__global__ void __launch_bounds__(256, 1) hgemm_kernel(float* __restrict__ out)
{
    const int batch = blockIdx.z;
    const int mt = blockIdx.y;
    int nh = g_nheavy[batch]; if (nh > HCAP) nh = HCAP;
    if (mt * 32 >= nh) return;
    const int j0 = blockIdx.x * 128;
    extern __shared__ float smf[];
    const uint32_t base = smem_u32(smf);
    const int tid = threadIdx.x;
    const int r = tid >> 3;
    const int cg = tid & 7;

    float acc[16];
    #pragma unroll
    for (int i = 0; i < 16; i++) acc[i] = 0.f;

    load_hchunk(base, 0, batch, mt, j0, 0, tid);
    asm volatile("cp.async.commit_group;" ::: "memory");
    load_hchunk(base, 1, batch, mt, j0, 1, tid);
    asm volatile("cp.async.commit_group;" ::: "memory");

    for (int ch = 0; ch < 64; ch++) {
        const int stage = ch & 1;
        if (ch < 63) asm volatile("cp.async.wait_group 1;" ::: "memory");
        else         asm volatile("cp.async.wait_group 0;" ::: "memory");
        __syncthreads();
        const float* V = smf + (size_t)stage * HCHUNK_FLOATS;
        const float* P = V + HVL_FLOATS;

        float wreg[32];
        #pragma unroll
        for (int q = 0; q < 8; q++) {
            float4 wv = *(const float4*)(P + r * HP_STRIDE + q * 4);
            wreg[q*4+0] = wv.x; wreg[q*4+1] = wv.y;
            wreg[q*4+2] = wv.z; wreg[q*4+3] = wv.w;
        }
        #pragma unroll
        for (int tt = 0; tt < 32; tt++) {
            const float w = wreg[tt];
            const float4* vr = (const float4*)(V + tt * 128 + cg * 16);
            float4 v0 = vr[0], v1 = vr[1], v2 = vr[2], v3 = vr[3];
            acc[0]  = fmaf(w, v0.x, acc[0]);  acc[1]  = fmaf(w, v0.y, acc[1]);
            acc[2]  = fmaf(w, v0.z, acc[2]);  acc[3]  = fmaf(w, v0.w, acc[3]);
            acc[4]  = fmaf(w, v1.x, acc[4]);  acc[5]  = fmaf(w, v1.y, acc[5]);
            acc[6]  = fmaf(w, v1.z, acc[6]);  acc[7]  = fmaf(w, v1.w, acc[7]);
            acc[8]  = fmaf(w, v2.x, acc[8]);  acc[9]  = fmaf(w, v2.y, acc[9]);
            acc[10] = fmaf(w, v2.z, acc[10]); acc[11] = fmaf(w, v2.w, acc[11]);
            acc[12] = fmaf(w, v3.x, acc[12]); acc[13] = fmaf(w, v3.y, acc[13]);
            acc[14] = fmaf(w, v3.z, acc[14]); acc[15] = fmaf(w, v3.w, acc[15]);
        }
        __syncthreads();
        if (ch + 2 < 64) {
            load_hchunk(base, stage, batch, mt, j0, ch + 2, tid);
            asm volatile("cp.async.commit_group;" ::: "memory");
        }
    }

    const int slot = mt * 32 + r;
    if (slot < nh) {
        const int srow = g_hidx[batch * SS + slot];
        const float invZ = 1.f / g_Zr[batch * HCAP + slot];
        float* op = out + ((size_t)(batch * SS + srow)) * HH + j0 + cg * 16;
        #pragma unroll
        for (int q = 0; q < 4; q++) {
            float4 o = { acc[q*4+0] * invZ, acc[q*4+1] * invZ,
                         acc[q*4+2] * invZ, acc[q*4+3] * invZ };
            ((float4*)op)[q] = o;
        }
    }
}

// ---------------------------------------------------------------------------
// K7: light rows — smem cache of top/bottom LCAP VL rows, warp-per-row
// ---------------------------------------------------------------------------
#define LIGHT_SMEM (2 * LCAP * 128 * 4 + 2 * LCAP * 4)

__global__ void __launch_bounds__(128, 1) light_kernel(float* __restrict__ out)
{
    const int rg = blockIdx.x;
    const int batch = rg >> 3;
    if (!g_uni[batch]) return;
    const int j0 = blockIdx.y * 128;
    extern __shared__ float smf[];
    float* cache = smf;
    int* s_si = (int*)(smf + 2 * LCAP * 128);
    const int tid = threadIdx.x, lane = tid & 31, wid = tid >> 5;

    if (tid < LCAP) {
        s_si[tid] = g_si[batch * SS + tid];
        s_si[LCAP + tid] = g_si[batch * SS + SS - 1 - tid];
    }
    __syncthreads();

    const uint32_t cbase = smem_u32(cache);
    #pragma unroll
    for (int i = 0; i < 64; i++) {
        int lin = tid + i * 128;
        int slot = lin >> 5;
        int c = (lin & 31) * 16;
        int t = s_si[slot];
        const char* src = (const char*)g_VL
            + ((size_t)(batch * SS + t) * HH + j0) * 4 + c;
        cp16(cbase + (uint32_t)(slot * 512 + c), src);
    }
    asm volatile("cp.async.commit_group;" ::: "memory");
    asm volatile("cp.async.wait_group 0;" ::: "memory");
    __syncthreads();

    const int row_base = rg * 256 + wid * 64;
    for (int rr = 0; rr < 64; rr++) {
        const int row = row_base + rr;
        const int cnt = g_cnt[row];
        if (cnt < 0) continue;
        const float a = g_a[row];
        const int bslot = (a > 0.f) ? 0 : LCAP;
        float w4[4];
        #pragma unroll
        for (int q = 0; q < 4; q++)
            w4[q] = g_wl[(size_t)row * LCAP + lane + q * 32];
        float acc0 = 0.f, acc1 = 0.f, acc2 = 0.f, acc3 = 0.f;
        for (int i = 0; i < cnt; i++) {
            float wi = __shfl_sync(0xffffffffu, w4[i >> 5], i & 31);
            const float* cr = cache + (size_t)(bslot + i) * 128;
            acc0 = fmaf(wi, cr[lane],      acc0);
            acc1 = fmaf(wi, cr[lane + 32], acc1);
            acc2 = fmaf(wi, cr[lane + 64], acc2);
            acc3 = fmaf(wi, cr[lane + 96], acc3);
        }
        const float invZ = 1.f / g_Z[row];
        float* op = out + (size_t)row * HH + j0;
        op[lane]      = acc0 * invZ;
        op[lane + 32] = acc1 * invZ;
        op[lane + 64] = acc2 * invZ;
        op[lane + 96] = acc3 * invZ;
    }
}

// ---------------------------------------------------------------------------
// K8: dense fallback (original attn) — only for non-uniform mask / overflow
// ---------------------------------------------------------------------------
__global__ void __launch_bounds__(128) attn_fallback_kernel(
    const float* __restrict__ mask, float* __restrict__ out)
{
    const int row   = blockIdx.x;
    const int batch = row >> 11;
    if (g_uni[batch] && g_cnt[row] != -2) return;
    const int tid   = threadIdx.x;
    const int lane  = tid & 31;
    const int wid   = tid >> 5;

    const float* bb = g_b + (batch << 11);
    const float* mm = mask + (batch << 11);
    const float  a  = g_a[row];

    __shared__ float s_red[4];
    __shared__ float s_w[SS];

    float lmax = -3.4e38f;
    #pragma unroll
    for (int c = 0; c < 16; c++) {
        int t = c * 128 + tid;
        lmax = fmaxf(lmax, fmaf(a, bb[t], mm[t]));
    }
    #pragma unroll
    for (int o = 16; o > 0; o >>= 1)
        lmax = fmaxf(lmax, __shfl_xor_sync(0xffffffffu, lmax, o));
    if (lane == 0) s_red[wid] = lmax;
    __syncthreads();
    const float gmax = fmaxf(fmaxf(s_red[0], s_red[1]),
                             fmaxf(s_red[2], s_red[3]));
    __syncthreads();

    float lsum = 0.f;
    #pragma unroll
    for (int c = 0; c < 16; c++) {
        int t = c * 128 + tid;
        float w = expf(fmaf(a, bb[t], mm[t]) - gmax);
        s_w[t] = w;
        lsum += w;
    }
    #pragma unroll
    for (int o = 16; o > 0; o >>= 1)
        lsum += __shfl_xor_sync(0xffffffffu, lsum, o);
    if (lane == 0) s_red[wid] = lsum;
    __syncthreads();
    const float tsum = s_red[0] + s_red[1] + s_red[2] + s_red[3];

    float acc0 = 0.f, acc1 = 0.f, acc2 = 0.f, acc3 = 0.f;
    float acc4 = 0.f, acc5 = 0.f, acc6 = 0.f, acc7 = 0.f;
    const int h0 = tid * 8;
    const float* vbase = g_VL + ((size_t)(batch << 11)) * HH + h0;
    for (int t = 0; t < SS; t++) {
        float w = s_w[t];
        const float4* v = (const float4*)(vbase + (size_t)t * HH);
        float4 v0 = v[0], v1 = v[1];
        acc0 = fmaf(w, v0.x, acc0); acc1 = fmaf(w, v0.y, acc1);
        acc2 = fmaf(w, v0.z, acc2); acc3 = fmaf(w, v0.w, acc3);
        acc4 = fmaf(w, v1.x, acc4); acc5 = fmaf(w, v1.y, acc5);
        acc6 = fmaf(w, v1.z, acc6); acc7 = fmaf(w, v1.w, acc7);
    }
    const float inv = 1.f / tsum;
    float4* op = (float4*)(out + (size_t)row * HH + h0);
    float4 o0 = { acc0*inv, acc1*inv, acc2*inv, acc3*inv };
    float4 o1 = { acc4*inv, acc5*inv, acc6*inv, acc7*inv };
    op[0] = o0;
    op[1] = o1;
}

// ---------------------------------------------------------------------------
extern "C" void kernel_launch(void* const* d_in, const int* in_sizes, int n_in,
                              void* d_out, int out_size)
{
    const float* hs      = (const float*)d_in[0];
    const float* mask    = (const float*)d_in[1];
    const float* value_w = (const float*)d_in[2];
    const float* value_b = (const float*)d_in[3];
    const float* U       = (const float*)d_in[4];
    const float* V       = (const float*)d_in[5];
    float* out = (float*)d_out;

    static bool attr_set = false;
    if (!attr_set) {
        cudaFuncSetAttribute(gemm_kernel,
            cudaFuncAttributeMaxDynamicSharedMemorySize, GEMM_SMEM_TOTAL);
        cudaFuncSetAttribute(hgemm_kernel,
            cudaFuncAttributeMaxDynamicSharedMemorySize, HG_SMEM);
        cudaFuncSetAttribute(light_kernel,
            cudaFuncAttributeMaxDynamicSharedMemorySize, LIGHT_SMEM);
        attr_set = true;
    }

    rank1_kernel<<<NROWS, 256>>>(hs, U, V);
    wconv_kernel<<<HH * HH / 4 / 256, 256>>>(value_w);
    gemm_kernel<<<(NROWS / 128) * (HH / 128), 256, GEMM_SMEM_TOTAL>>>(value_b);
    sort_kernel<<<BB, 1024>>>(mask);
    classify_kernel<<<NROWS, LCAP>>>();
    pdense_kernel<<<dim3(HCAP, BB), 256>>>();
    hgemm_kernel<<<dim3(8, HCAP / 32, BB), 256, HG_SMEM>>>(out);
    light_kernel<<<dim3(32, 8), 128, LIGHT_SMEM>>>(out);
    attn_fallback_kernel<<<NROWS, 128>>>(mask, out);
}

// round 16
// speedup vs baseline: 2.3065x; 2.3065x over previous
#include <cuda_runtime.h>
#include <cuda_bf16.h>
#include <cstdint>

#define BB 4
#define SS 2048
#define HH 1024
#define NROWS (BB*SS)

// ---------------------------------------------------------------------------
// Static device scratch
// ---------------------------------------------------------------------------
__device__ __align__(256) float g_VL[(size_t)NROWS * HH];
__device__ float g_a[NROWS];
__device__ float g_b[NROWS];
__device__ __align__(256) __nv_bfloat16 g_Ah[(size_t)NROWS * HH];
__device__ __align__(256) __nv_bfloat16 g_Al[(size_t)NROWS * HH];
__device__ __align__(256) __nv_bfloat16 g_Wh[(size_t)HH * HH];
__device__ __align__(256) __nv_bfloat16 g_Wl[(size_t)HH * HH];
// attention scratch
__device__ float g_sb[BB * SS];   // b sorted desc per batch
__device__ int   g_si[BB * SS];   // sorted t indices
__device__ int   g_uni[BB];       // mask-uniform flag
__device__ int   g_cnt[NROWS];    // active prefix length per row
__device__ float g_Z[NROWS];      // softmax partition per row
__device__ int   g_rkey[NROWS];   // row sort key (dir, count)
__device__ int   g_rsi[BB * SS];  // rows sorted by key (local row id)

// ---------------------------------------------------------------------------
// helpers
// ---------------------------------------------------------------------------
__device__ __forceinline__ uint32_t smem_u32(const void* p) {
    uint32_t a;
    asm("{ .reg .u64 t; cvta.to.shared.u64 t, %1; cvt.u32.u64 %0, t; }"
        : "=r"(a) : "l"(p));
    return a;
}
__device__ __forceinline__ void cp16(uint32_t dst, const void* src) {
    asm volatile("cp.async.cg.shared.global [%0], [%1], 16;"
                 :: "r"(dst), "l"(src) : "memory");
}
__device__ __forceinline__ void ldsm_x4(uint32_t& r0, uint32_t& r1,
                                        uint32_t& r2, uint32_t& r3,
                                        uint32_t addr) {
    asm volatile("ldmatrix.sync.aligned.m8n8.x4.shared.b16 {%0,%1,%2,%3}, [%4];"
                 : "=r"(r0), "=r"(r1), "=r"(r2), "=r"(r3) : "r"(addr) : "memory");
}
__device__ __forceinline__ void mma_bf16(float* c, const uint32_t* a,
                                         const uint32_t* b) {
    asm volatile(
        "mma.sync.aligned.m16n8k16.row.col.f32.bf16.bf16.f32 "
        "{%0,%1,%2,%3}, {%4,%5,%6,%7}, {%8,%9}, {%0,%1,%2,%3};"
        : "+f"(c[0]), "+f"(c[1]), "+f"(c[2]), "+f"(c[3])
        : "r"(a[0]), "r"(a[1]), "r"(a[2]), "r"(a[3]), "r"(b[0]), "r"(b[1]));
}
__device__ __forceinline__ uint32_t swz128(uint32_t off) {
    return off ^ ((off >> 3) & 0x70);
}

// ---------------------------------------------------------------------------
// K1: rank-1 vectors + hi/lo bf16 split of hs
// ---------------------------------------------------------------------------
__global__ void __launch_bounds__(256) rank1_kernel(
    const float* __restrict__ hs, const float* __restrict__ U,
    const float* __restrict__ V)
{
    const int row = blockIdx.x;
    const int tid = threadIdx.x;
    const float4 h = ((const float4*)(hs + (size_t)row * HH))[tid];

    __nv_bfloat16 h0 = __float2bfloat16(h.x);
    __nv_bfloat16 h1 = __float2bfloat16(h.y);
    __nv_bfloat16 h2 = __float2bfloat16(h.z);
    __nv_bfloat16 h3 = __float2bfloat16(h.w);
    __nv_bfloat162* ph = (__nv_bfloat162*)(g_Ah + (size_t)row * HH + tid * 4);
    __nv_bfloat162* pl = (__nv_bfloat162*)(g_Al + (size_t)row * HH + tid * 4);
    ph[0] = __halves2bfloat162(h0, h1);
    ph[1] = __halves2bfloat162(h2, h3);
    pl[0] = __halves2bfloat162(
        __float2bfloat16(h.x - __bfloat162float(h0)),
        __float2bfloat16(h.y - __bfloat162float(h1)));
    pl[1] = __halves2bfloat162(
        __float2bfloat16(h.z - __bfloat162float(h2)),
        __float2bfloat16(h.w - __bfloat162float(h3)));

    const float4 u = ((const float4*)U)[tid];
    const float4 v = ((const float4*)V)[tid];
    float su = h.x * u.x + h.y * u.y + h.z * u.z + h.w * u.w;
    float sv = h.x * v.x + h.y * v.y + h.z * v.z + h.w * v.w;
    #pragma unroll
    for (int o = 16; o > 0; o >>= 1) {
        su += __shfl_xor_sync(0xffffffffu, su, o);
        sv += __shfl_xor_sync(0xffffffffu, sv, o);
    }
    __shared__ float s_u[8], s_v[8];
    if ((tid & 31) == 0) { s_u[tid >> 5] = su; s_v[tid >> 5] = sv; }
    __syncthreads();
    if (tid == 0) {
        float tu = 0.f, tv = 0.f;
        #pragma unroll
        for (int i = 0; i < 8; i++) { tu += s_u[i]; tv += s_v[i]; }
        g_a[row] = (tu + U[HH]) * 0.125f;
        g_b[row] = tv + V[HH];
    }
}

// ---------------------------------------------------------------------------
// K1b: hi/lo split of value_w
// ---------------------------------------------------------------------------
__global__ void __launch_bounds__(256) wconv_kernel(const float* __restrict__ w)
{
    const int idx = blockIdx.x * 256 + threadIdx.x;
    const float4 x = ((const float4*)w)[idx];
    __nv_bfloat16 h0 = __float2bfloat16(x.x);
    __nv_bfloat16 h1 = __float2bfloat16(x.y);
    __nv_bfloat16 h2 = __float2bfloat16(x.z);
    __nv_bfloat16 h3 = __float2bfloat16(x.w);
    __nv_bfloat162* ph = (__nv_bfloat162*)(g_Wh + (size_t)idx * 4);
    __nv_bfloat162* pl = (__nv_bfloat162*)(g_Wl + (size_t)idx * 4);
    ph[0] = __halves2bfloat162(h0, h1);
    ph[1] = __halves2bfloat162(h2, h3);
    pl[0] = __halves2bfloat162(
        __float2bfloat16(x.x - __bfloat162float(h0)),
        __float2bfloat16(x.y - __bfloat162float(h1)));
    pl[1] = __halves2bfloat162(
        __float2bfloat16(x.z - __bfloat162float(h2)),
        __float2bfloat16(x.w - __bfloat162float(h3)));
}

// ---------------------------------------------------------------------------
// K2: value projection bf16x3 GEMM (proven, unchanged)
// ---------------------------------------------------------------------------
#define AH_OFF 0
#define AL_OFF 16384
#define WH_OFF 32768
#define WL_OFF 49152
#define STAGE_BYTES 65536
#define GEMM_SMEM_TOTAL (2 * STAGE_BYTES)

__device__ __forceinline__ void load_slab(uint32_t sb, int bm, int bn, int k0,
                                          int tid)
{
    const char* a_h = (const char*)g_Ah + (size_t)bm * 2048 + k0 * 2;
    const char* a_l = (const char*)g_Al + (size_t)bm * 2048 + k0 * 2;
    const char* w_h = (const char*)g_Wh + (size_t)bn * 2048 + k0 * 2;
    const char* w_l = (const char*)g_Wl + (size_t)bn * 2048 + k0 * 2;
    #pragma unroll
    for (int i = 0; i < 4; i++) {
        int cid = tid + i * 256;
        int row = cid >> 3;
        int c16 = (cid & 7) * 16;
        uint32_t swz = swz128((uint32_t)(row * 128 + c16));
        size_t goff = (size_t)row * 2048 + c16;
        cp16(sb + AH_OFF + swz, a_h + goff);
        cp16(sb + AL_OFF + swz, a_l + goff);
        cp16(sb + WH_OFF + swz, w_h + goff);
        cp16(sb + WL_OFF + swz, w_l + goff);
    }
}

__global__ void __launch_bounds__(256, 1)
gemm_kernel(const float* __restrict__ bias)
{
    extern __shared__ char smem[];
    const uint32_t smem_base = smem_u32(smem);
    const int tid  = threadIdx.x;
    const int wid  = tid >> 5;
    const int lane = tid & 31;
    const int bm = (blockIdx.x >> 3) * 128;
    const int bn = (blockIdx.x & 7) * 128;
    const int warp_m = (wid & 1) * 64;
    const int warp_n = (wid >> 1) * 32;
    const uint32_t st0 = smem_base;
    const uint32_t st1 = smem_base + STAGE_BYTES;

    float acc[4][4][4];
    #pragma unroll
    for (int i = 0; i < 4; i++)
        #pragma unroll
        for (int j = 0; j < 4; j++)
            #pragma unroll
            for (int q = 0; q < 4; q++) acc[i][j][q] = 0.f;

    uint32_t a_base[4];
    #pragma unroll
    for (int mf = 0; mf < 4; mf++)
        a_base[mf] = swz128((uint32_t)(
            (warp_m + mf * 16 + (lane & 15)) * 128 + ((lane >> 4) & 1) * 16));
    uint32_t b_base[2];
    #pragma unroll
    for (int p = 0; p < 2; p++)
        b_base[p] = swz128((uint32_t)(
            (warp_n + p * 16 + (lane & 7) + ((lane & 16) >> 1)) * 128
            + ((lane & 8) ? 16u : 0u)));

    load_slab(st0, bm, bn, 0, tid);
    asm volatile("cp.async.commit_group;" ::: "memory");
    load_slab(st1, bm, bn, 64, tid);
    asm volatile("cp.async.commit_group;" ::: "memory");

    for (int j = 0; j < 16; j++) {
        const uint32_t sb = (j & 1) ? st1 : st0;
        if (j < 15) asm volatile("cp.async.wait_group 1;" ::: "memory");
        else        asm volatile("cp.async.wait_group 0;" ::: "memory");
        __syncthreads();
        #pragma unroll
        for (int ks = 0; ks < 4; ks++) {
            const uint32_t kso = (uint32_t)(ks * 32);
            uint32_t af[4][4], bh[4][2], bl[4][2];
            #pragma unroll
            for (int mf = 0; mf < 4; mf++)
                ldsm_x4(af[mf][0], af[mf][1], af[mf][2], af[mf][3],
                        sb + AH_OFF + (a_base[mf] ^ kso));
            #pragma unroll
            for (int p = 0; p < 2; p++)
                ldsm_x4(bh[2*p][0], bh[2*p][1], bh[2*p+1][0], bh[2*p+1][1],
                        sb + WH_OFF + (b_base[p] ^ kso));
            #pragma unroll
            for (int mf = 0; mf < 4; mf++)
                #pragma unroll
                for (int nf = 0; nf < 4; nf++)
                    mma_bf16(acc[mf][nf], af[mf], bh[nf]);
            #pragma unroll
            for (int p = 0; p < 2; p++)
                ldsm_x4(bl[2*p][0], bl[2*p][1], bl[2*p+1][0], bl[2*p+1][1],
                        sb + WL_OFF + (b_base[p] ^ kso));
            #pragma unroll
            for (int mf = 0; mf < 4; mf++)
                #pragma unroll
                for (int nf = 0; nf < 4; nf++)
                    mma_bf16(acc[mf][nf], af[mf], bl[nf]);
            #pragma unroll
            for (int mf = 0; mf < 4; mf++)
                ldsm_x4(af[mf][0], af[mf][1], af[mf][2], af[mf][3],
                        sb + AL_OFF + (a_base[mf] ^ kso));
            #pragma unroll
            for (int mf = 0; mf < 4; mf++)
                #pragma unroll
                for (int nf = 0; nf < 4; nf++)
                    mma_bf16(acc[mf][nf], af[mf], bh[nf]);
        }
        __syncthreads();
        if (j + 2 < 16) {
            load_slab(sb, bm, bn, (j + 2) * 64, tid);
            asm volatile("cp.async.commit_group;" ::: "memory");
        }
    }

    const int r0 = bm + warp_m + (lane >> 2);
    const int c0 = bn + warp_n + 2 * (lane & 3);
    #pragma unroll
    for (int nf = 0; nf < 4; nf++) {
        const int c = c0 + nf * 8;
        const float b0 = bias[c], b1 = bias[c + 1];
        #pragma unroll
        for (int mf = 0; mf < 4; mf++) {
            const int r = r0 + mf * 16;
            float2 v0 = { acc[mf][nf][0] + b0, acc[mf][nf][1] + b1 };
            float2 v1 = { acc[mf][nf][2] + b0, acc[mf][nf][3] + b1 };
            *(float2*)(g_VL + (size_t)r * HH + c)       = v0;
            *(float2*)(g_VL + (size_t)(r + 8) * HH + c) = v1;
        }
    }
}

// ---------------------------------------------------------------------------
// K3: per-batch bitonic sort of b (descending) + mask-uniformity flag
// ---------------------------------------------------------------------------
__global__ void __launch_bounds__(1024) sort_kernel(const float* __restrict__ mask)
{
    __shared__ float sb[SS];
    __shared__ int   si[SS];
    __shared__ int   sflag;
    const int batch = blockIdx.x;
    const int tid = threadIdx.x;
    if (tid == 0) sflag = 1;
    __syncthreads();
    const float m0 = mask[batch * SS];
    #pragma unroll
    for (int q = 0; q < 2; q++) {
        int i = tid + q * 1024;
        sb[i] = g_b[batch * SS + i];
        si[i] = i;
        if (mask[batch * SS + i] != m0) atomicAnd(&sflag, 0);
    }
    __syncthreads();
    for (int k = 2; k <= SS; k <<= 1) {
        for (int j = k >> 1; j > 0; j >>= 1) {
            #pragma unroll
            for (int q = 0; q < 2; q++) {
                int i = tid + q * 1024;
                int ixj = i ^ j;
                if (ixj > i) {
                    bool up = ((i & k) == 0);
                    float bi = sb[i], bj = sb[ixj];
                    int ii = si[i], ij = si[ixj];
                    bool less = (bi < bj) || (bi == bj && ii > ij);
                    if (less == up) {
                        sb[i] = bj; sb[ixj] = bi;
                        si[i] = ij; si[ixj] = ii;
                    }
                }
            }
            __syncthreads();
        }
    }
    #pragma unroll
    for (int q = 0; q < 2; q++) {
        int i = tid + q * 1024;
        g_sb[batch * SS + i] = sb[i];
        g_si[batch * SS + i] = si[i];
    }
    if (tid == 0) g_uni[batch] = sflag;
}

// ---------------------------------------------------------------------------
// K4: per-row count (active prefix length), partition Z, row sort key
// ---------------------------------------------------------------------------
__global__ void __launch_bounds__(128) countz_kernel()
{
    const int row = blockIdx.x;
    const int batch = row >> 11;
    if (!g_uni[batch]) return;
    const int tid = threadIdx.x;
    const int lane = tid & 31, wid = tid >> 5;
    const float a = g_a[row];
    const float* sb = g_sb + batch * SS;
    const float bmax = sb[0], bmin = sb[SS - 1];
    __shared__ float red[4];

    int count; float M;
    if (a == 0.f) { count = SS; M = 0.f; }
    else if (a > 0.f) {
        float thr = bmax - 40.f / a;
        int lo = 0, hi = SS;
        while (lo < hi) { int mid = (lo + hi) >> 1;
                          if (sb[mid] >= thr) lo = mid + 1; else hi = mid; }
        count = lo; M = a * bmax;
    } else {
        float thr = bmin + 40.f / (-a);
        int lo = 0, hi = SS;
        while (lo < hi) { int mid = (lo + hi) >> 1;
                          if (sb[mid] > thr) lo = mid + 1; else hi = mid; }
        count = SS - lo; M = a * bmin;
    }

    float s = 0.f;
    for (int r = tid; r < count; r += 128) {
        float sv = (a >= 0.f) ? sb[r] : sb[SS - 1 - r];
        s += expf(fmaf(a, sv, -M));
    }
    #pragma unroll
    for (int o = 16; o > 0; o >>= 1) s += __shfl_xor_sync(0xffffffffu, s, o);
    if (lane == 0) red[wid] = s;
    __syncthreads();
    if (tid == 0) {
        g_Z[row] = red[0] + red[1] + red[2] + red[3];
        g_cnt[row] = count;
        g_rkey[row] = (a >= 0.f) ? count : count + 3000;
    }
}

// ---------------------------------------------------------------------------
// K5: per-batch bitonic sort of rows by (dir,count) key, ascending
// ---------------------------------------------------------------------------
__global__ void __launch_bounds__(1024) rowsort_kernel()
{
    __shared__ int sk[SS];
    __shared__ int sr[SS];
    const int batch = blockIdx.x;
    if (!g_uni[batch]) return;
    const int tid = threadIdx.x;
    #pragma unroll
    for (int q = 0; q < 2; q++) {
        int i = tid + q * 1024;
        sk[i] = g_rkey[batch * SS + i];
        sr[i] = i;
    }
    __syncthreads();
    for (int k = 2; k <= SS; k <<= 1) {
        for (int j = k >> 1; j > 0; j >>= 1) {
            #pragma unroll
            for (int q = 0; q < 2; q++) {
                int i = tid + q * 1024;
                int ixj = i ^ j;
                if (ixj > i) {
                    bool up = ((i & k) == 0);
                    int ki = sk[i], kj = sk[ixj];
                    int ri = sr[i], rj = sr[ixj];
                    bool gt = (ki > kj) || (ki == kj && ri > rj);
                    if (gt == up) {
                        sk[i] = kj; sk[ixj] = ki;
                        sr[i] = rj; sr[ixj] = ri;
                    }
                }
            }
            __syncthreads();
        }
    }
    #pragma unroll
    for (int q = 0; q < 2; q++) {
        int i = tid + q * 1024;
        g_rsi[batch * SS + i] = sr[i];
    }
}

// ---------------------------------------------------------------------------
// K6: attention — 8 count-sorted rows per block share the sorted-t prefix.
// 256 threads; thread owns cols [tid*4, tid*4+4) for all 8 rows.
// ---------------------------------------------------------------------------
__global__ void __launch_bounds__(256, 4) attn2_kernel(float* __restrict__ out)
{
    const int batch = blockIdx.x >> 8;
    if (!g_uni[batch]) return;
    const int grp = blockIdx.x & 255;
    const int tid = threadIdx.x;
    const int q8 = tid >> 5;          // which of 8 rows this thread's w-slot is
    const int i32 = tid & 31;         // rank-within-chunk for w computation

    __shared__ int   s_srow[8];
    __shared__ float s_aM[8][2];      // a, M
    __shared__ int   s_dir[8];
    __shared__ float s_invZ[8];
    __shared__ int   s_maxc[2];
    __shared__ float s_w[8][32];
    __shared__ int   s_t[32];

    if (tid < 8) {
        int srow = g_rsi[batch * SS + grp * 8 + tid];
        int row = (batch << 11) + srow;
        float a = g_a[row];
        const float* sb = g_sb + batch * SS;
        s_srow[tid] = srow;
        s_aM[tid][0] = a;
        s_aM[tid][1] = (a >= 0.f) ? a * sb[0] : a * sb[SS - 1];
        s_dir[tid] = (a >= 0.f) ? 0 : 1;
        s_invZ[tid] = 1.f / g_Z[row];
    }
    if (tid == 8) { s_maxc[0] = 0; s_maxc[1] = 0; }
    __syncthreads();
    if (tid < 8) {
        int row = (batch << 11) + s_srow[tid];
        atomicMax(&s_maxc[s_dir[tid]], g_cnt[row]);
    }
    __syncthreads();

    const float* sb = g_sb + batch * SS;
    const int*   si = g_si + batch * SS;
    const float* vl = g_VL + (size_t)(batch << 11) * HH;

    float4 acc[8];
    #pragma unroll
    for (int q = 0; q < 8; q++) acc[q] = make_float4(0.f, 0.f, 0.f, 0.f);

    const float a_q = s_aM[q8][0];
    const float M_q = s_aM[q8][1];
    const int dir_q = s_dir[q8];

    #pragma unroll
    for (int d = 0; d < 2; d++) {
        const int maxc = s_maxc[d];
        for (int c0 = 0; c0 < maxc; c0 += 32) {
            __syncthreads();
            const int rank = c0 + i32;
            if (tid < 32) {
                int rk = (rank < SS) ? rank : 0;
                s_t[i32] = (d == 0) ? si[rk] : si[SS - 1 - rk];
            }
            float w = 0.f;
            if (dir_q == d && rank < maxc) {
                float sv = (d == 0) ? sb[rank] : sb[SS - 1 - rank];
                w = expf(fmaf(a_q, sv, -M_q));
            }
            s_w[q8][i32] = w;
            __syncthreads();

            #pragma unroll 8
            for (int i = 0; i < 32; i++) {
                const int t = s_t[i];
                const float4 v = *(const float4*)(vl + (size_t)t * HH + tid * 4);
                #pragma unroll
                for (int q = 0; q < 8; q++) {
                    const float wq = s_w[q][i];
                    acc[q].x = fmaf(wq, v.x, acc[q].x);
                    acc[q].y = fmaf(wq, v.y, acc[q].y);
                    acc[q].z = fmaf(wq, v.z, acc[q].z);
                    acc[q].w = fmaf(wq, v.w, acc[q].w);
                }
            }
        }
    }

    #pragma unroll
    for (int q = 0; q < 8; q++) {
        const float z = s_invZ[q];
        float4 o = { acc[q].x * z, acc[q].y * z, acc[q].z * z, acc[q].w * z };
        *(float4*)(out + ((size_t)(batch << 11) + s_srow[q]) * HH + tid * 4) = o;
    }
}

// ---------------------------------------------------------------------------
// K7: dense fallback — only when mask non-uniform (early exit otherwise)
// ---------------------------------------------------------------------------
__global__ void __launch_bounds__(128) attn_fallback_kernel(
    const float* __restrict__ mask, float* __restrict__ out)
{
    const int row   = blockIdx.x;
    const int batch = row >> 11;
    if (g_uni[batch]) return;
    const int tid   = threadIdx.x;
    const int lane  = tid & 31;
    const int wid   = tid >> 5;

    const float* bb = g_b + (batch << 11);
    const float* mm = mask + (batch << 11);
    const float  a  = g_a[row];

    __shared__ float s_red[4];
    __shared__ float s_w[SS];

    float lmax = -3.4e38f;
    #pragma unroll
    for (int c = 0; c < 16; c++) {
        int t = c * 128 + tid;
        lmax = fmaxf(lmax, fmaf(a, bb[t], mm[t]));
    }
    #pragma unroll
    for (int o = 16; o > 0; o >>= 1)
        lmax = fmaxf(lmax, __shfl_xor_sync(0xffffffffu, lmax, o));
    if (lane == 0) s_red[wid] = lmax;
    __syncthreads();
    const float gmax = fmaxf(fmaxf(s_red[0], s_red[1]),
                             fmaxf(s_red[2], s_red[3]));
    __syncthreads();

    float lsum = 0.f;
    #pragma unroll
    for (int c = 0; c < 16; c++) {
        int t = c * 128 + tid;
        float w = expf(fmaf(a, bb[t], mm[t]) - gmax);
        s_w[t] = w;
        lsum += w;
    }
    #pragma unroll
    for (int o = 16; o > 0; o >>= 1)
        lsum += __shfl_xor_sync(0xffffffffu, lsum, o);
    if (lane == 0) s_red[wid] = lsum;
    __syncthreads();
    const float tsum = s_red[0] + s_red[1] + s_red[2] + s_red[3];

    float acc0 = 0.f, acc1 = 0.f, acc2 = 0.f, acc3 = 0.f;
    float acc4 = 0.f, acc5 = 0.f, acc6 = 0.f, acc7 = 0.f;
    const int h0 = tid * 8;
    const float* vbase = g_VL + ((size_t)(batch << 11)) * HH + h0;
    for (int t = 0; t < SS; t++) {
        float w = s_w[t];
        const float4* v = (const float4*)(vbase + (size_t)t * HH);
        float4 v0 = v[0], v1 = v[1];
        acc0 = fmaf(w, v0.x, acc0); acc1 = fmaf(w, v0.y, acc1);
        acc2 = fmaf(w, v0.z, acc2); acc3 = fmaf(w, v0.w, acc3);
        acc4 = fmaf(w, v1.x, acc4); acc5 = fmaf(w, v1.y, acc5);
        acc6 = fmaf(w, v1.z, acc6); acc7 = fmaf(w, v1.w, acc7);
    }
    const float inv = 1.f / tsum;
    float4* op = (float4*)(out + (size_t)row * HH + h0);
    float4 o0 = { acc0*inv, acc1*inv, acc2*inv, acc3*inv };
    float4 o1 = { acc4*inv, acc5*inv, acc6*inv, acc7*inv };
    op[0] = o0;
    op[1] = o1;
}

// ---------------------------------------------------------------------------
extern "C" void kernel_launch(void* const* d_in, const int* in_sizes, int n_in,
                              void* d_out, int out_size)
{
    const float* hs      = (const float*)d_in[0];
    const float* mask    = (const float*)d_in[1];
    const float* value_w = (const float*)d_in[2];
    const float* value_b = (const float*)d_in[3];
    const float* U       = (const float*)d_in[4];
    const float* V       = (const float*)d_in[5];
    float* out = (float*)d_out;

    static bool attr_set = false;
    if (!attr_set) {
        cudaFuncSetAttribute(gemm_kernel,
            cudaFuncAttributeMaxDynamicSharedMemorySize, GEMM_SMEM_TOTAL);
        attr_set = true;
    }

    rank1_kernel<<<NROWS, 256>>>(hs, U, V);
    wconv_kernel<<<HH * HH / 4 / 256, 256>>>(value_w);
    gemm_kernel<<<(NROWS / 128) * (HH / 128), 256, GEMM_SMEM_TOTAL>>>(value_b);
    sort_kernel<<<BB, 1024>>>(mask);
    countz_kernel<<<NROWS, 128>>>();
    rowsort_kernel<<<BB, 1024>>>();
    attn2_kernel<<<NROWS / 8, 256>>>(out);
    attn_fallback_kernel<<<NROWS, 128>>>(mask, out);
}